// round 8
// baseline (speedup 1.0000x reference)
#include <cuda_runtime.h>
#include <cuda_fp16.h>
#include <math.h>

// SigmoidGatedCRFLoss — pairwise-collapsed, fp16/half2 pipeline, dy-split.
// loss = [ Σ_{p,q} md(p)·ms(q)·G(Δ)·(0.9·e^{-50|Δrgb|²}+0.1)·(s_p(1-s_q)+s_q(1-s_p)) ] / max(Σ md,1)
// Per pixel:  num_p = md_p·(s_p·SB + (1-s_p)·SA),  SA=Σ w·A, SB=Σ w·B, A=ms·s, B=ms·(1-s)
//   w = G9·(e + 1/9),  G9 = 0.9·exp(-(dx²+dy²)/72) (0 at center)
//   e  = 2^(-Σ du²), u = rgb · sqrt(50·log2 e)  ==  exp(-50·|Δrgb|²)

#define RAD    5
#define DIAM   11
#define BX     32           // lanes: one warp spans a full smem row
#define BY     4
#define TW     (BX * 2)     // 64-px-wide tile, 2 px per thread
#define TH     BY           // 4
#define HW_    (TW + 2*RAD) // 74 halo cols
#define HROWS  9            // max halo rows per dy-half (TH + 6 - 1)
#define HC     38           // half2 per row (37 used, +1 pad)
#define NT     (BX * BY)    // 128 threads

#define RGB_SCALE 8.4932178f   // sqrt(50 * log2(e))

__device__ double   g_num;
__device__ double   g_den;
__device__ unsigned g_ticket;

__global__ __launch_bounds__(NT, 8) void crf_loss_kernel(
    const float* __restrict__ x,      // [N,3,H,W]
    const float* __restrict__ y,      // [N,H,W]
    const float* __restrict__ msrc,   // [N,1,H,W]
    const float* __restrict__ mdst,   // [N,1,H,W]
    float* __restrict__ out,
    int H, int W, unsigned nblocks)
{
    // SoA fp16 halo; each warp row-access is unit-stride -> conflict-free
    __shared__ __half2 sR [HROWS][HC];
    __shared__ __half2 sGg[HROWS][HC];
    __shared__ __half2 sBb[HROWS][HC];
    __shared__ __half2 sA [HROWS][HC];
    __shared__ __half2 sB [HROWS][HC];
    __shared__ __half2 sGp0[DIAM][6];   // pixel0 weight pairs (g[2k], g[2k+1])
    __shared__ __half2 sGp1[DIAM][6];   // pixel1 weight pairs (g[2k-1], g[2k])
    __shared__ float   red[8];

    const int zz   = blockIdx.z;
    const int n    = zz >> 1;
    const int half = zz & 1;
    const int d0   = half ? 6 : 0;       // dy range [d0, d0+nDy)
    const int nDy  = half ? 5 : 6;
    const int tx0  = blockIdx.x * TW;
    const int ty0  = blockIdx.y * TH;
    const int cx   = threadIdx.x;        // 0..31
    const int cy   = threadIdx.y;        // 0..3
    const int tid  = cy * BX + cx;
    const int HWp  = H * W;

    const float* __restrict__ xr = x + (size_t)n * 3 * HWp;
    const float* __restrict__ xg = xr + HWp;
    const float* __restrict__ xb = xr + 2 * HWp;
    const float* __restrict__ yp = y    + (size_t)n * HWp;
    const float* __restrict__ mp = msrc + (size_t)n * HWp;
    const float* __restrict__ dp = mdst + (size_t)n * HWp;

    // Spatial gaussian weight pairs; g(dx,dy)=0.9*exp(-((dx-5)^2+(dy-5)^2)/72),
    // center zeroed, out-of-range dx -> 0 (pads the shifted pixel1/pixel0 pairs).
    for (int i = tid; i < DIAM * 6; i += NT) {
        int row = i / 6, k = i % 6;
        int ddy = row - RAD;
        float gv[3];                     // dx = 2k-1, 2k, 2k+1
        #pragma unroll
        for (int t = 0; t < 3; t++) {
            int dx = 2 * k - 1 + t;
            float g = 0.0f;
            if (dx >= 0 && dx < DIAM) {
                int ddx = dx - RAD;
                g = 0.9f * __expf(-(float)(ddx * ddx + ddy * ddy) * (1.0f / 72.0f));
                if (ddx == 0 && ddy == 0) g = 0.0f;
            }
            gv[t] = g;
        }
        sGp0[row][k] = __floats2half2_rn(gv[1], gv[2]);
        sGp1[row][k] = __floats2half2_rn(gv[0], gv[1]);
    }

    // Halo fill (fp16). OOB -> zeros == unfold's zero padding of binarized mask.
    const int hRows = TH + nDy - 1;      // 9 (half0) / 8 (half1)
    const int hsz   = HW_ * hRows;
    __half* hR  = (__half*)sR;
    __half* hG  = (__half*)sGg;
    __half* hB  = (__half*)sBb;
    __half* hA  = (__half*)sA;
    __half* hBB = (__half*)sB;
    for (int i = tid; i < hsz; i += NT) {
        int ly = i / HW_;
        int lx = i - ly * HW_;
        int gy = ty0 + d0 - RAD + ly;
        int gx = tx0 + lx - RAD;
        float r = 0.f, g = 0.f, b = 0.f, A = 0.f, B = 0.f;
        if (gx >= 0 && gx < W && gy >= 0 && gy < H) {
            int idx = gy * W + gx;
            float ms = mp[idx];
            if (isnan(ms) || ms < 1.0f) ms = 0.0f;   // binarize, keep value if >=1
            float s = 1.0f / (1.0f + __expf(-yp[idx]));
            r = xr[idx] * RGB_SCALE;
            g = xg[idx] * RGB_SCALE;
            b = xb[idx] * RGB_SCALE;
            A = ms * s;
            B = ms - A;                              // ms*(1-s)
        }
        int o = ly * (2 * HC) + lx;
        hR[o]  = __float2half_rn(r);
        hG[o]  = __float2half_rn(g);
        hB[o]  = __float2half_rn(b);
        hA[o]  = __float2half_rn(A);
        hBB[o] = __float2half_rn(B);
    }
    __syncthreads();

    const int px0 = tx0 + 2 * cx;
    const int py  = ty0 + cy;

    // Centers from gmem, quantized through the SAME fp16 rounding as the halo.
    __half2 c0r, c0g, c0b, c1r, c1g, c1b;
    {
        int i0 = py * W + px0;
        c0r = __float2half2_rn(xr[i0] * RGB_SCALE);
        c0g = __float2half2_rn(xg[i0] * RGB_SCALE);
        c0b = __float2half2_rn(xb[i0] * RGB_SCALE);
        c1r = __float2half2_rn(xr[i0 + 1] * RGB_SCALE);
        c1g = __float2half2_rn(xg[i0 + 1] * RGB_SCALE);
        c1b = __float2half2_rn(xb[i0 + 1] * RGB_SCALE);
    }
    const __half2 NINTH2 = __float2half2_rn(1.0f / 9.0f);
    const __half2 ZERO2  = __float2half2_rn(0.0f);

    float SA0 = 0.f, SB0 = 0.f, SA1 = 0.f, SB1 = 0.f;

    #define TAPP(qr,qg,qb,qa,qbb,cr,cg,cb,Gp,RA,RB) do {                     \
        __half2 dr_ = __hsub2(qr, cr);                                       \
        __half2 dg_ = __hsub2(qg, cg);                                       \
        __half2 db_ = __hsub2(qb, cb);                                       \
        __half2 t_  = __hmul2(dr_, __hneg2(dr_));                            \
        t_ = __hfma2(dg_, __hneg2(dg_), t_);                                 \
        t_ = __hfma2(db_, __hneg2(db_), t_);                                 \
        __half2 e_ = h2exp2(t_);                                             \
        __half2 w_ = __hmul2(__hadd2(e_, NINTH2), Gp);                       \
        RA = __hfma2(w_, qa, RA);                                            \
        RB = __hfma2(w_, qbb, RB);                                           \
    } while (0)

    for (int dyi = 0; dyi < nDy; dyi++) {
        const int row  = cy + dyi;         // halo-local row
        const int grow = d0 + dyi;         // gaussian-table row
        const __half2* __restrict__ pr  = &sR [row][cx];
        const __half2* __restrict__ pg  = &sGg[row][cx];
        const __half2* __restrict__ pb  = &sBb[row][cx];
        const __half2* __restrict__ pa  = &sA [row][cx];
        const __half2* __restrict__ pbb = &sB [row][cx];
        const __half2* __restrict__ g0  = sGp0[grow];
        const __half2* __restrict__ g1  = sGp1[grow];

        __half2 ra0 = ZERO2, rb0 = ZERO2, ra1 = ZERO2, rb1 = ZERO2;
        #pragma unroll
        for (int k = 0; k < 6; k++) {
            __half2 qr  = pr[k];
            __half2 qg  = pg[k];
            __half2 qb  = pb[k];
            __half2 qa  = pa[k];
            __half2 qbb = pbb[k];
            TAPP(qr, qg, qb, qa, qbb, c0r, c0g, c0b, g0[k], ra0, rb0);
            TAPP(qr, qg, qb, qa, qbb, c1r, c1g, c1b, g1[k], ra1, rb1);
        }
        // Row-partial fp16 -> fp32 spill (bounds fp16 accumulation error)
        float2 f;
        f = __half22float2(ra0); SA0 += f.x + f.y;
        f = __half22float2(rb0); SB0 += f.x + f.y;
        f = __half22float2(ra1); SA1 += f.x + f.y;
        f = __half22float2(rb1); SB1 += f.x + f.y;
    }

    // Center combine (partial over this dy-half; linear in SA/SB)
    float num = 0.f, den = 0.f;
    if (py < H && px0 < W) {
        {
            int idx = py * W + px0;
            float md = dp[idx];
            if (isnan(md) || md < 1.0f) md = 0.0f;
            float sp = 1.0f / (1.0f + __expf(-yp[idx]));
            num += md * fmaf(sp, SB0, (1.0f - sp) * SA0);
            if (half == 0) den += md;              // denominator counted once
        }
        if (px0 + 1 < W) {
            int idx = py * W + px0 + 1;
            float md = dp[idx];
            if (isnan(md) || md < 1.0f) md = 0.0f;
            float sp = 1.0f / (1.0f + __expf(-yp[idx]));
            num += md * fmaf(sp, SB1, (1.0f - sp) * SA1);
            if (half == 0) den += md;
        }
    }

    // Block reduction
    #pragma unroll
    for (int off = 16; off > 0; off >>= 1) {
        num += __shfl_down_sync(0xffffffffu, num, off);
        den += __shfl_down_sync(0xffffffffu, den, off);
    }
    int wid = tid >> 5, lid = tid & 31;
    if (lid == 0) { red[wid] = num; red[4 + wid] = den; }
    __syncthreads();

    if (tid == 0) {
        float ns = red[0] + red[1] + red[2] + red[3];
        float ds = red[4] + red[5] + red[6] + red[7];
        atomicAdd(&g_num, (double)ns);
        atomicAdd(&g_den, (double)ds);
        __threadfence();
        unsigned old = atomicAdd(&g_ticket, 1u);
        if (old == nblocks - 1u) {           // last block finalizes + resets
            double nn = g_num;
            double dd = g_den;
            if (dd < 1.0) dd = 1.0;
            out[0] = (float)(nn / dd);
            g_num = 0.0;
            g_den = 0.0;
            g_ticket = 0u;
        }
    }
}

extern "C" void kernel_launch(void* const* d_in, const int* in_sizes, int n_in,
                              void* d_out, int out_size) {
    const float* x    = (const float*)d_in[0];
    const float* y    = (const float*)d_in[1];
    const float* msrc = (const float*)d_in[2];
    const float* mdst = (const float*)d_in[3];
    float* out = (float*)d_out;

    const int H = 256, W = 256;
    const int N = in_sizes[1] / (H * W);

    dim3 block(BX, BY, 1);
    dim3 grid((W + TW - 1) / TW, (H + TH - 1) / TH, 2 * N);  // dy-split halves
    unsigned nblocks = grid.x * grid.y * grid.z;
    crf_loss_kernel<<<grid, block>>>(x, y, msrc, mdst, out, H, W, nblocks);
}

// round 9
// speedup vs baseline: 1.2569x; 1.2569x over previous
#include <cuda_runtime.h>
#include <math.h>

// SigmoidGatedCRFLoss — symmetric-pair halved formulation, fp32, dy-split.
//
// loss = [ Σ_{unordered pairs {p,q}} w(p,q)·(P_p B_q + Q_p A_q + P_q B_p + Q_q A_p) ] / max(Σ md, 1)
//   P = md·s, Q = md·(1-s), A = ms·s, B = ms·(1-s), s = sigmoid(y)
//   w = G9(Δ)·(e + 1/9),  G9 = 0.9·exp(-(dx²+dy²)/72)  (0 at center)
//   e = 2^(-Σ du²), u = rgb·sqrt(50·log2 e)  == exp(-50·|Δrgb|²)
// Each pixel p claims pairs with q ∈ {dy>0} ∪ {dy=0, dx>0}  (60 taps, half of 121).
// Out-of-image q -> zero smem entry -> both pair sides vanish (matches unfold zero-pad).

#define RAD    5
#define BX     16           // threads in x
#define BY     8            // threads in y
#define TW     32           // tile width (2 px / thread)
#define TH     8
#define HW_    (TW + 2*RAD) // 42
#define HALFW  21
#define HROWS  10           // halo rows per dy-half (TH + 3 - 1)
#define NT     (BX * BY)    // 128

#define RGB_SCALE 8.4932178f  // sqrt(50 * log2(e))

__device__ double   g_num;
__device__ double   g_den;
__device__ unsigned g_ticket;

__device__ __forceinline__ float fast_ex2(float v) {
    float r;
    asm("ex2.approx.f32 %0, %1;" : "=f"(r) : "f"(v));
    return r;
}

__global__ __launch_bounds__(NT, 8) void crf_loss_kernel(
    const float* __restrict__ x,      // [N,3,H,W]
    const float* __restrict__ y,      // [N,H,W]
    const float* __restrict__ msrc,   // [N,1,H,W]
    const float* __restrict__ mdst,   // [N,1,H,W]
    float* __restrict__ out,
    int H, int W, unsigned nblocks)
{
    // even/odd column split -> unit-stride lane addressing (no bank conflicts)
    __shared__ float4 sFEv[HROWS][HALFW];   // r,g,b (scaled), A = ms*s
    __shared__ float4 sFOd[HROWS][HALFW];
    __shared__ float4 sSEv[HROWS][HALFW];   // B = ms*(1-s), P = md*s, Q = md*(1-s)
    __shared__ float4 sSOd[HROWS][HALFW];
    __shared__ __align__(16) float sG0[6][12];  // center0 weights, row dyy, col j (dx=j-5)
    __shared__ __align__(16) float sG1[6][12];  // center1 weights (dx=j-6)
    __shared__ float red[8];

    const int zz    = blockIdx.z;
    const int n     = zz >> 1;
    const int half  = zz & 1;
    const int rbase = half ? 3 : 0;      // dyy range [rbase, rbase+3)
    const int tx0   = blockIdx.x * TW;
    const int ty0   = blockIdx.y * TH;
    const int cx    = threadIdx.x;       // 0..15
    const int cy    = threadIdx.y;       // 0..7
    const int tid   = cy * BX + cx;
    const int HWp   = H * W;

    const float* __restrict__ xr = x + (size_t)n * 3 * HWp;
    const float* __restrict__ xg = xr + HWp;
    const float* __restrict__ xb = xr + 2 * HWp;
    const float* __restrict__ yp = y    + (size_t)n * HWp;
    const float* __restrict__ mp = msrc + (size_t)n * HWp;
    const float* __restrict__ dp = mdst + (size_t)n * HWp;

    // Claimed-set gaussian tables: dyy in [0,6); claimed = (dyy>0) || (dx>0).
    // Center (0,0) excluded (dy0 requires dx>=1) == kernels[:,:,center]=0.
    for (int i = tid; i < 6 * 12; i += NT) {
        int dyy = i / 12, j = i % 12;
        float g0 = 0.f, g1 = 0.f;
        {
            int dx = j - 5;                      // center0
            if (dx >= -5 && dx <= 5 && (dyy > 0 || dx > 0))
                g0 = 0.9f * __expf(-(float)(dx * dx + dyy * dyy) * (1.0f / 72.0f));
        }
        {
            int dx = j - 6;                      // center1
            if (dx >= -5 && dx <= 5 && (dyy > 0 || dx > 0))
                g1 = 0.9f * __expf(-(float)(dx * dx + dyy * dyy) * (1.0f / 72.0f));
        }
        sG0[dyy][j] = g0;
        sG1[dyy][j] = g1;
    }

    // Halo fill: rows gy = ty0 + rbase + ly, ly in [0, HROWS). OOB -> zeros.
    for (int i = tid; i < HW_ * HROWS; i += NT) {
        int ly = i / HW_;
        int lx = i - ly * HW_;
        int gy = ty0 + rbase + ly;
        int gx = tx0 + lx - RAD;
        float r = 0.f, g = 0.f, b = 0.f, A = 0.f, B = 0.f, P = 0.f, Q = 0.f;
        if (gx >= 0 && gx < W && gy >= 0 && gy < H) {
            int idx = gy * W + gx;
            float ms = mp[idx];
            if (isnan(ms) || ms < 1.0f) ms = 0.0f;   // binarize, keep value if >=1
            float md = dp[idx];
            if (isnan(md) || md < 1.0f) md = 0.0f;
            float s = 1.0f / (1.0f + __expf(-yp[idx]));
            r = xr[idx] * RGB_SCALE;
            g = xg[idx] * RGB_SCALE;
            b = xb[idx] * RGB_SCALE;
            A = ms * s;  B = ms - A;
            P = md * s;  Q = md - P;
        }
        float4 F = make_float4(r, g, b, A);
        float4 S = make_float4(B, P, Q, 0.f);
        int h = lx >> 1;
        if (lx & 1) { sFOd[ly][h] = F; sSOd[ly][h] = S; }
        else        { sFEv[ly][h] = F; sSEv[ly][h] = S; }
    }
    __syncthreads();

    const int px0 = tx0 + 2 * cx;
    const int py  = ty0 + cy;

    // Center rgb from gmem (L1/L2-cached; center row not in half1's halo)
    float c0r, c0g, c0b, c1r, c1g, c1b;
    {
        int i0 = py * W + px0;
        c0r = xr[i0] * RGB_SCALE;      c1r = xr[i0 + 1] * RGB_SCALE;
        c0g = xg[i0] * RGB_SCALE;      c1g = xg[i0 + 1] * RGB_SCALE;
        c0b = xb[i0] * RGB_SCALE;      c1b = xb[i0 + 1] * RGB_SCALE;
    }

    float SA0 = 0.f, SB0 = 0.f, SP0 = 0.f, SQ0 = 0.f;
    float SA1 = 0.f, SB1 = 0.f, SP1 = 0.f, SQ1 = 0.f;

    #define TAP4(qF, qS, Gv, cr, cg, cb, SA, SB, SP, SQ) do {                \
        float dr_ = (qF).x - (cr);                                           \
        float dg_ = (qF).y - (cg);                                           \
        float db_ = (qF).z - (cb);                                           \
        float d2n_ = fmaf(dr_, -dr_, fmaf(dg_, -dg_, db_ * (-db_)));         \
        float w_ = (fast_ex2(d2n_) + 0.11111111f) * (Gv);                    \
        SA = fmaf(w_, (qF).w, SA);                                           \
        SB = fmaf(w_, (qS).x, SB);                                           \
        SP = fmaf(w_, (qS).y, SP);                                           \
        SQ = fmaf(w_, (qS).z, SQ);                                           \
    } while (0)

    #pragma unroll
    for (int t = 0; t < 3; t++) {
        const int dyy = rbase + t;               // 0..5
        const int ly  = cy + t;                  // halo-local row
        const float4* __restrict__ ev  = &sFEv[ly][cx];
        const float4* __restrict__ od  = &sFOd[ly][cx];
        const float4* __restrict__ ev2 = &sSEv[ly][cx];
        const float4* __restrict__ od2 = &sSOd[ly][cx];

        float gr0[12], gr1[12];
        ((float4*)gr0)[0] = *(const float4*)&sG0[dyy][0];
        ((float4*)gr0)[1] = *(const float4*)&sG0[dyy][4];
        ((float4*)gr0)[2] = *(const float4*)&sG0[dyy][8];
        ((float4*)gr1)[0] = *(const float4*)&sG1[dyy][0];
        ((float4*)gr1)[1] = *(const float4*)&sG1[dyy][4];
        ((float4*)gr1)[2] = *(const float4*)&sG1[dyy][8];

        // dy=0 row (only exists in half0, t=0): claimed taps live at j>=6 only.
        const int jstart = (half == 0 && t == 0) ? 6 : 0;

        #pragma unroll
        for (int j = 0; j < 12; j++) {
            if (j < jstart) continue;
            // window col (local) = 2cx + j; even j -> Ev[cx+j/2], odd -> Od[cx+(j-1)/2]
            float4 qF, qS;
            if (j & 1) { qF = od[(j - 1) >> 1]; qS = od2[(j - 1) >> 1]; }
            else       { qF = ev[j >> 1];       qS = ev2[j >> 1];       }
            if (j < 11) TAP4(qF, qS, gr0[j], c0r, c0g, c0b, SA0, SB0, SP0, SQ0);
            if (j > 0)  TAP4(qF, qS, gr1[j], c1r, c1g, c1b, SA1, SB1, SP1, SQ1);
        }
    }

    // Center combine: num_p = P_p·SB + Q_p·SA + B_p·SP + A_p·SQ (linear -> half-splittable)
    float num = 0.f, den = 0.f;
    {
        int i0 = py * W + px0;
        {
            float ms = mp[i0];
            if (isnan(ms) || ms < 1.0f) ms = 0.0f;
            float md = dp[i0];
            if (isnan(md) || md < 1.0f) md = 0.0f;
            float s = 1.0f / (1.0f + __expf(-yp[i0]));
            float A = ms * s, B = ms - A, P = md * s, Q = md - P;
            num += P * SB0 + Q * SA0 + B * SP0 + A * SQ0;
            if (half == 0) den += md;            // denominator counted once
        }
        {
            float ms = mp[i0 + 1];
            if (isnan(ms) || ms < 1.0f) ms = 0.0f;
            float md = dp[i0 + 1];
            if (isnan(md) || md < 1.0f) md = 0.0f;
            float s = 1.0f / (1.0f + __expf(-yp[i0 + 1]));
            float A = ms * s, B = ms - A, P = md * s, Q = md - P;
            num += P * SB1 + Q * SA1 + B * SP1 + A * SQ1;
            if (half == 0) den += md;
        }
    }

    // Block reduction
    #pragma unroll
    for (int off = 16; off > 0; off >>= 1) {
        num += __shfl_down_sync(0xffffffffu, num, off);
        den += __shfl_down_sync(0xffffffffu, den, off);
    }
    int wid = tid >> 5, lid = tid & 31;
    if (lid == 0) { red[wid] = num; red[4 + wid] = den; }
    __syncthreads();

    if (tid == 0) {
        float ns = red[0] + red[1] + red[2] + red[3];
        float ds = red[4] + red[5] + red[6] + red[7];
        atomicAdd(&g_num, (double)ns);
        atomicAdd(&g_den, (double)ds);
        __threadfence();
        unsigned old = atomicAdd(&g_ticket, 1u);
        if (old == nblocks - 1u) {               // last block finalizes + resets
            double nn = g_num;
            double dd = g_den;
            if (dd < 1.0) dd = 1.0;
            out[0] = (float)(nn / dd);
            g_num = 0.0;
            g_den = 0.0;
            g_ticket = 0u;
        }
    }
}

extern "C" void kernel_launch(void* const* d_in, const int* in_sizes, int n_in,
                              void* d_out, int out_size) {
    const float* x    = (const float*)d_in[0];
    const float* y    = (const float*)d_in[1];
    const float* msrc = (const float*)d_in[2];
    const float* mdst = (const float*)d_in[3];
    float* out = (float*)d_out;

    const int H = 256, W = 256;
    const int N = in_sizes[1] / (H * W);

    dim3 block(BX, BY, 1);
    dim3 grid((W + TW - 1) / TW, (H + TH - 1) / TH, 2 * N);  // dy-halves of the claimed set
    unsigned nblocks = grid.x * grid.y * grid.z;
    crf_loss_kernel<<<grid, block>>>(x, y, msrc, mdst, out, H, W, nblocks);
}